// round 3
// baseline (speedup 1.0000x reference)
#include <cuda_runtime.h>

#define CB 2
#define CC 128
#define CCK 64
#define CH 256
#define CW 512
#define CH2 128
#define CW2 256
#define HWF (CH*CW)       // 131072
#define HW2 (CH2*CW2)     // 32768
#define NPIXF (CB*HWF)    // 262144
#define NPIX2 (CB*HW2)    // 65536

#define CTY 4
#define CTX 16
#define HY (CTY+2)        // 6
#define HX (CTX+2)        // 18
#define NH (HY*HX)        // 108

typedef unsigned long long ull;

// ---- f32x2 packed-math helpers (sm_103a FFMA2 path) ----
__device__ __forceinline__ ull fma2(ull a, ull b, ull c) {
    ull d;
    asm("fma.rn.f32x2 %0, %1, %2, %3;" : "=l"(d) : "l"(a), "l"(b), "l"(c));
    return d;
}
__device__ __forceinline__ ull pk2(float x) {          // broadcast {x,x}
    ull r;
    asm("mov.b64 %0, {%1, %1};" : "=l"(r) : "f"(x));
    return r;
}
__device__ __forceinline__ ull pk2p(float x, float y) { // pack {x,y}
    ull r;
    asm("mov.b64 %0, {%1, %2};" : "=l"(r) : "f"(x), "f"(y));
    return r;
}
__device__ __forceinline__ float2 upk(ull v) {
    float2 o;
    asm("mov.b64 {%0, %1}, %2;" : "=f"(o.x), "=f"(o.y) : "l"(v));
    return o;
}
__device__ __forceinline__ ull ld2(const float* p) {   // LDS.64 / LDG.64
    return *reinterpret_cast<const ull*>(p);
}

// Scratch (device globals: allocation-free)
__device__ float g_k[NPIX2*CCK];            // coarse k, NHWC [p][64]
__device__ float g_v[NPIX2*CC];             // coarse v, NHWC [p][128]
__device__ float g_q[(size_t)NPIXF*CCK];    // fine q, NHWC [p][64]
__device__ float g_x[(size_t)NPIXF*CC];     // attention out, NHWC [p][128]
__device__ float g_Wc[CC*CC];               // Wout @ Wvi
__device__ float g_beff[CC];                // Wout @ bvi + bout

// ---------------------------------------------------------------------------
// K0: fuse weights  Wc = Wout @ Wvi, beff = Wout @ bvi + bout
// ---------------------------------------------------------------------------
__global__ void k_fuse(const float* __restrict__ Wout, const float* __restrict__ Wvi,
                       const float* __restrict__ bvi, const float* __restrict__ bout) {
    int o = blockIdx.x, i = threadIdx.x;
    float acc = 0.f;
    for (int m = 0; m < CC; m++) acc += Wout[o*CC + m] * Wvi[m*CC + i];
    g_Wc[o*CC + i] = acc;
    if (i == 0) {
        float b = bout[o];
        for (int m = 0; m < CC; m++) b += Wout[o*CC + m] * bvi[m];
        g_beff[o] = b;
    }
}

// ---------------------------------------------------------------------------
// K1: coarse k,v = [Wk; Wvp] @ h_prev. 192 out ch, 64 px/block, f32x2 math.
// Wt transposed [k=128][r=192] pitch 194; Xs [128][64]; smem = 132096 B
// ---------------------------------------------------------------------------
#define KV_WP 194
__global__ void k_kv(const float* __restrict__ hp,
                     const float* __restrict__ Wk, const float* __restrict__ bk,
                     const float* __restrict__ Wvp, const float* __restrict__ bvp) {
    extern __shared__ float sm[];
    float* Wt = sm;                 // [128][194]
    float* Xs = sm + 128*KV_WP;     // [128][64]
    int t = threadIdx.x;

    for (int idx = t; idx < 192*CC; idx += 256) {
        int r = idx >> 7, k = idx & 127;
        float w = (r < CCK) ? Wk[r*CC + k] : Wvp[(r - CCK)*CC + k];
        Wt[k*KV_WP + r] = w;
    }
    int p0 = blockIdx.x * 64;
    int b = p0 / HW2, s0 = p0 % HW2;
    const float* base = hp + (size_t)b*CC*HW2 + s0;
    for (int idx = t; idx < CC*64; idx += 256) {
        int c = idx >> 6, p = idx & 63;
        Xs[c*64 + p] = base[(size_t)c*HW2 + p];
    }
    __syncthreads();

    int ty = t >> 4, tx = t & 15;            // ty: 16 ch-groups(12ch=6 pairs), tx: 16 px-groups(4 px)
    ull acc[6][4];
    #pragma unroll
    for (int i = 0; i < 6; i++) {
        int r = 2*ty + 32*i;
        ull binit = (r < CCK) ? ld2(&bk[r]) : ld2(&bvp[r - CCK]);
        #pragma unroll
        for (int j = 0; j < 4; j++) acc[i][j] = binit;
    }
    for (int k = 0; k < CC; k++) {
        ull yv[4];
        #pragma unroll
        for (int j = 0; j < 4; j++) yv[j] = pk2(Xs[k*64 + tx + 16*j]);
        #pragma unroll
        for (int i = 0; i < 6; i++) {
            ull wv = ld2(&Wt[k*KV_WP + 2*ty + 32*i]);
            #pragma unroll
            for (int j = 0; j < 4; j++) acc[i][j] = fma2(wv, yv[j], acc[i][j]);
        }
    }
    __syncthreads();

    float* Os = sm;  // [192][65], aliases Wt
    #pragma unroll
    for (int i = 0; i < 6; i++) {
        int r = 2*ty + 32*i;
        #pragma unroll
        for (int j = 0; j < 4; j++) {
            float2 v = upk(acc[i][j]);
            Os[r*65 + tx + 16*j]       = v.x;
            Os[(r + 1)*65 + tx + 16*j] = v.y;
        }
    }
    __syncthreads();

    float* gk = g_k + (size_t)p0*CCK;
    for (int idx = t; idx < CCK*64; idx += 256) {
        int p = idx >> 6, c = idx & 63;
        gk[p*CCK + c] = Os[c*65 + p];
    }
    float* gv = g_v + (size_t)p0*CC;
    for (int idx = t; idx < CC*64; idx += 256) {
        int p = idx >> 7, c = idx & 127;
        gv[p*CC + c] = Os[(CCK + c)*65 + p];
    }
}

// ---------------------------------------------------------------------------
// K2: q = Wq @ h_init. 64 out ch, 64 px/block, f32x2 math.
// Wt [128][66] + Xs [128][64]; smem = 66560 B
// ---------------------------------------------------------------------------
#define Q_WP 66
__global__ void k_q(const float* __restrict__ hi,
                    const float* __restrict__ Wq, const float* __restrict__ bq) {
    extern __shared__ float sm[];
    float* Wt = sm;                // [128][66]
    float* Xs = sm + 128*Q_WP;     // [128][64]
    int t = threadIdx.x;

    for (int idx = t; idx < CCK*CC; idx += 256) {
        int r = idx >> 7, k = idx & 127;
        Wt[k*Q_WP + r] = Wq[r*CC + k];
    }
    int p0 = blockIdx.x * 64;
    int b = p0 / HWF, s0 = p0 % HWF;
    const float* base = hi + (size_t)b*CC*HWF + s0;
    for (int idx = t; idx < CC*64; idx += 256) {
        int c = idx >> 6, p = idx & 63;
        Xs[c*64 + p] = base[(size_t)c*HWF + p];
    }
    __syncthreads();

    int ty = t >> 5, tx = t & 31;  // ty: 8 ch-groups(8ch=4 pairs), tx: 32 px-groups(2 px)
    ull acc[4][2];
    #pragma unroll
    for (int i = 0; i < 4; i++) {
        ull binit = ld2(&bq[2*ty + 16*i]);
        #pragma unroll
        for (int j = 0; j < 2; j++) acc[i][j] = binit;
    }
    for (int k = 0; k < CC; k++) {
        ull yv[2];
        #pragma unroll
        for (int j = 0; j < 2; j++) yv[j] = pk2(Xs[k*64 + tx + 32*j]);
        #pragma unroll
        for (int i = 0; i < 4; i++) {
            ull wv = ld2(&Wt[k*Q_WP + 2*ty + 16*i]);
            #pragma unroll
            for (int j = 0; j < 2; j++) acc[i][j] = fma2(wv, yv[j], acc[i][j]);
        }
    }
    __syncthreads();

    float* Os = sm;  // [64][65], aliases Wt
    #pragma unroll
    for (int i = 0; i < 4; i++) {
        int r = 2*ty + 16*i;
        #pragma unroll
        for (int j = 0; j < 2; j++) {
            float2 v = upk(acc[i][j]);
            Os[r*65 + tx + 32*j]       = v.x;
            Os[(r + 1)*65 + tx + 32*j] = v.y;
        }
    }
    __syncthreads();

    float* gq = g_q + (size_t)p0*CCK;
    for (int idx = t; idx < CCK*64; idx += 256) {
        int p = idx >> 6, c = idx & 63;
        gq[p*CCK + c] = Os[c*65 + p];
    }
}

// ---------------------------------------------------------------------------
// K3: attention. Block = 4x16 coarse tile (8x32 fine = 256 px). f32x2 math.
// smem: ks[108][66] + vs[108][132] + as[256][12] = 97824 B  -> 2 blocks/SM
// q streamed from gmem (no smem tile). Zero halo == unfold zero-padding.
// ---------------------------------------------------------------------------
#define KP 66
#define VP 132
__global__ void k_attn() {
    extern __shared__ float sm[];
    float* ks = sm;                 // [108][66]
    float* vs = ks + NH*KP;         // [108][132]
    float* as = vs + NH*VP;         // [256][12]
    int t = threadIdx.x;
    int b = blockIdx.z;
    int cy0 = blockIdx.y * CTY, cx0 = blockIdx.x * CTX;
    int fy0 = cy0*2, fx0 = cx0*2;

    for (int idx = t; idx < NH*CCK; idx += 256) {
        int pix = idx >> 6, c = idx & 63;
        int hy = pix / HX, hx = pix % HX;
        int gy = cy0 + hy - 1, gx = cx0 + hx - 1;
        float v = 0.f;
        if ((unsigned)gy < CH2 && (unsigned)gx < CW2)
            v = g_k[((size_t)(b*HW2 + gy*CW2 + gx))*CCK + c];
        ks[pix*KP + c] = v;
    }
    for (int idx = t; idx < NH*CC; idx += 256) {
        int pix = idx >> 7, c = idx & 127;
        int hy = pix / HX, hx = pix % HX;
        int gy = cy0 + hy - 1, gx = cx0 + hx - 1;
        float v = 0.f;
        if ((unsigned)gy < CH2 && (unsigned)gx < CW2)
            v = g_v[((size_t)(b*HW2 + gy*CW2 + gx))*CC + c];
        vs[pix*VP + c] = v;
    }
    __syncthreads();

    // Phase A: one thread per fine pixel; q streamed from gmem (float4),
    // 9 packed scores + softmax.
    {
        int p = t;
        int fy = p >> 5, fx = p & 31;
        int cy = fy >> 1, cx = fx >> 1;
        const float4* gq = reinterpret_cast<const float4*>(
            g_q + ((size_t)((b*CH + fy0 + fy)*CW + fx0 + fx))*CCK);
        const float* kb = ks + (cy*HX + cx)*KP;
        ull sc2[9];
        #pragma unroll
        for (int j = 0; j < 9; j++) sc2[j] = 0ull;
        #pragma unroll 4
        for (int cc = 0; cc < 16; cc++) {
            float4 q4 = gq[cc];
            ull qa = pk2p(q4.x, q4.y);
            ull qb = pk2p(q4.z, q4.w);
            int c = cc*4;
            #pragma unroll
            for (int dy = 0; dy < 3; dy++)
                #pragma unroll
                for (int dx = 0; dx < 3; dx++) {
                    int j = dy*3 + dx;
                    const float* kp = kb + (dy*HX + dx)*KP + c;
                    sc2[j] = fma2(qa, ld2(kp), sc2[j]);
                    sc2[j] = fma2(qb, ld2(kp + 2), sc2[j]);
                }
        }
        float sc[9];
        #pragma unroll
        for (int j = 0; j < 9; j++) { float2 v = upk(sc2[j]); sc[j] = v.x + v.y; }
        float m = sc[0];
        #pragma unroll
        for (int j = 1; j < 9; j++) m = fmaxf(m, sc[j]);
        float s = 0.f;
        #pragma unroll
        for (int j = 0; j < 9; j++) { sc[j] = __expf(sc[j] - m); s += sc[j]; }
        float inv = 1.f / s;
        #pragma unroll
        for (int j = 0; j < 9; j++) as[p*12 + j] = sc[j]*inv;
    }
    __syncthreads();

    // Phase B: 32 passes; each pass: 8 px x 128 ch. Thread owns (px, 4 ch).
    int pl = t >> 5, cg = t & 31;
    for (int pass = 0; pass < 32; pass++) {
        int p = pass*8 + pl;
        int fy = p >> 5, fx = p & 31;
        int cy = fy >> 1, cx = fx >> 1;
        const float* ap = as + p*12;
        const float* vb = vs + (cy*HX + cx)*VP + cg*4;
        ull acc0 = 0ull, acc1 = 0ull;
        #pragma unroll
        for (int dy = 0; dy < 3; dy++)
            #pragma unroll
            for (int dx = 0; dx < 3; dx++) {
                int j = dy*3 + dx;
                ull a2 = pk2(ap[j]);
                const float* vp = vb + (dy*HX + dx)*VP;
                acc0 = fma2(a2, ld2(vp),     acc0);
                acc1 = fma2(a2, ld2(vp + 2), acc1);
            }
        float2 r0 = upk(acc0), r1 = upk(acc1);
        float4 o4 = make_float4(r0.x, r0.y, r1.x, r1.y);
        *reinterpret_cast<float4*>(
            &g_x[((size_t)((b*CH + fy0 + fy)*CW + fx0 + fx))*CC + cg*4]) = o4;
    }
}

// ---------------------------------------------------------------------------
// K4: out = [Wc | Wout] @ [h_init; x] + beff. K=256, 64 px/block, f32x2 math.
// Wf transposed [k=256][o=128] pitch 130 + Ys [256][65]; smem = 199680 B
// ---------------------------------------------------------------------------
#define O_WP 130
__global__ void k_out(const float* __restrict__ hi, const float* __restrict__ Wout,
                      float* __restrict__ out) {
    extern __shared__ float sm[];
    float* Wf = sm;                 // [256][130]
    float* Ys = sm + 256*O_WP;      // [256][65]
    int t = threadIdx.x;

    for (int idx = t; idx < CC*CC; idx += 256) {
        int o = idx >> 7, i = idx & 127;
        Wf[i*O_WP + o]          = g_Wc[idx];
        Wf[(128 + i)*O_WP + o]  = Wout[idx];
    }
    int p0 = blockIdx.x * 64;
    int b = p0 / HWF, s0 = p0 % HWF;
    const float* base = hi + (size_t)b*CC*HWF + s0;
    for (int idx = t; idx < CC*64; idx += 256) {
        int c = idx >> 6, p = idx & 63;
        Ys[c*65 + p] = base[(size_t)c*HWF + p];
    }
    const float* xb = g_x + (size_t)p0*CC;
    for (int idx = t; idx < CC*64; idx += 256) {
        int c = idx & 127, p = idx >> 7;
        Ys[(CC + c)*65 + p] = xb[p*CC + c];
    }
    __syncthreads();

    int ty = t >> 4, tx = t & 15;  // ty: 16 ch-groups(8ch=4 pairs), tx: 16 px-groups(4 px)
    ull acc[4][4];
    #pragma unroll
    for (int i = 0; i < 4; i++) {
        ull binit = ld2(&g_beff[2*ty + 32*i]);
        #pragma unroll
        for (int j = 0; j < 4; j++) acc[i][j] = binit;
    }
    for (int k = 0; k < 256; k++) {
        ull yv[4];
        #pragma unroll
        for (int j = 0; j < 4; j++) yv[j] = pk2(Ys[k*65 + tx + 16*j]);
        #pragma unroll
        for (int i = 0; i < 4; i++) {
            ull wv = ld2(&Wf[k*O_WP + 2*ty + 32*i]);
            #pragma unroll
            for (int j = 0; j < 4; j++) acc[i][j] = fma2(wv, yv[j], acc[i][j]);
        }
    }

    float* ob = out + (size_t)b*CC*HWF + s0;
    #pragma unroll
    for (int i = 0; i < 4; i++) {
        int r = 2*ty + 32*i;
        #pragma unroll
        for (int j = 0; j < 4; j++) {
            float2 v = upk(acc[i][j]);
            ob[(size_t)r*HWF + tx + 16*j]       = v.x;
            ob[(size_t)(r + 1)*HWF + tx + 16*j] = v.y;
        }
    }
}

// ---------------------------------------------------------------------------
extern "C" void kernel_launch(void* const* d_in, const int* in_sizes, int n_in,
                              void* d_out, int out_size) {
    const float* h_prev = (const float*)d_in[0];
    const float* h_init = (const float*)d_in[1];
    const float* Wq   = (const float*)d_in[2];
    const float* bq   = (const float*)d_in[3];
    const float* Wk   = (const float*)d_in[4];
    const float* bk   = (const float*)d_in[5];
    const float* Wvp  = (const float*)d_in[6];
    const float* bvp  = (const float*)d_in[7];
    const float* Wvi  = (const float*)d_in[8];
    const float* bvi  = (const float*)d_in[9];
    const float* Wout = (const float*)d_in[10];
    const float* bout = (const float*)d_in[11];
    float* out = (float*)d_out;

    cudaFuncSetAttribute(k_kv,   cudaFuncAttributeMaxDynamicSharedMemorySize, 128*KV_WP*4 + 128*64*4);
    cudaFuncSetAttribute(k_q,    cudaFuncAttributeMaxDynamicSharedMemorySize, 128*Q_WP*4 + 128*64*4);
    cudaFuncSetAttribute(k_attn, cudaFuncAttributeMaxDynamicSharedMemorySize, (NH*KP + NH*VP + 256*12)*4);
    cudaFuncSetAttribute(k_out,  cudaFuncAttributeMaxDynamicSharedMemorySize, 256*O_WP*4 + 256*65*4);

    k_fuse<<<CC, CC>>>(Wout, Wvi, bvi, bout);
    k_kv<<<NPIX2/64, 256, 128*KV_WP*4 + 128*64*4>>>(h_prev, Wk, bk, Wvp, bvp);
    k_q<<<NPIXF/64, 256, 128*Q_WP*4 + 128*64*4>>>(h_init, Wq, bq);
    dim3 ag(CW2/CTX, CH2/CTY, CB);
    k_attn<<<ag, 256, (NH*KP + NH*VP + 256*12)*4>>>();
    k_out<<<NPIXF/64, 256, 256*O_WP*4 + 256*65*4>>>(h_init, Wout, out);
}

// round 4
// speedup vs baseline: 2.6627x; 2.6627x over previous
#include <cuda_runtime.h>
#include <cuda_bf16.h>
#include <cstdint>

#define CB 2
#define CC 128
#define CCK 64
#define CH 256
#define CW 512
#define CH2 128
#define CW2 256
#define HWF (CH*CW)
#define HW2 (CH2*CW2)
#define NPIXF (CB*HWF)
#define NPIX2 (CB*HW2)
#define GRD 148

#define CTY 4
#define CTX 16
#define HX 18
#define NH 108
#define KP 66
#define VP 133
#define AP 13

typedef unsigned long long ull;
typedef unsigned int u32;

__device__ __forceinline__ ull fma2(ull a, ull b, ull c) {
    ull d; asm("fma.rn.f32x2 %0, %1, %2, %3;" : "=l"(d) : "l"(a), "l"(b), "l"(c)); return d;
}
__device__ __forceinline__ ull pk2(float x) {
    ull r; asm("mov.b64 %0, {%1, %1};" : "=l"(r) : "f"(x)); return r;
}
__device__ __forceinline__ ull pk2p(float x, float y) {
    ull r; asm("mov.b64 %0, {%1, %2};" : "=l"(r) : "f"(x), "f"(y)); return r;
}
__device__ __forceinline__ float2 upk(ull v) {
    float2 o; asm("mov.b64 {%0, %1}, %2;" : "=f"(o.x), "=f"(o.y) : "l"(v)); return o;
}
__device__ __forceinline__ ull ld2(const float* p) { return *reinterpret_cast<const ull*>(p); }

__device__ __forceinline__ void ldsm4(u32* r, const __nv_bfloat16* p) {
    u32 sa = (u32)__cvta_generic_to_shared(p);
    asm volatile("ldmatrix.sync.aligned.m8n8.x4.shared.b16 {%0,%1,%2,%3}, [%4];"
        : "=r"(r[0]), "=r"(r[1]), "=r"(r[2]), "=r"(r[3]) : "r"(sa));
}
__device__ __forceinline__ void mma16816(float* c, const u32* a, u32 b0, u32 b1) {
    asm volatile("mma.sync.aligned.m16n8k16.row.col.f32.bf16.bf16.f32 "
        "{%0,%1,%2,%3}, {%4,%5,%6,%7}, {%8,%9}, {%0,%1,%2,%3};"
        : "+f"(c[0]), "+f"(c[1]), "+f"(c[2]), "+f"(c[3])
        : "r"(a[0]), "r"(a[1]), "r"(a[2]), "r"(a[3]), "r"(b0), "r"(b1));
}
__device__ __forceinline__ u32 cvt2(float hiF, float loF) {
    u32 r; asm("cvt.rn.bf16x2.f32 %0, %1, %2;" : "=r"(r) : "f"(hiF), "f"(loF)); return r;
}
__device__ __forceinline__ void cpa16(void* dst, const void* src) {
    u32 d = (u32)__cvta_generic_to_shared(dst);
    asm volatile("cp.async.cg.shared.global [%0], [%1], 16;" :: "r"(d), "l"(src));
}
#define CPA_COMMIT() asm volatile("cp.async.commit_group;")
#define CPA_WAIT1()  asm volatile("cp.async.wait_group 1;")

__device__ float g_k[(size_t)NPIX2*CCK];
__device__ float g_v[(size_t)NPIX2*CC];
__device__ float g_q[(size_t)NPIXF*CCK];
__device__ float g_x[(size_t)NPIXF*CC];   // NCHW
__device__ float g_Wc[CC*CC];
__device__ float g_beff[CC];

__global__ void k_fuse(const float* __restrict__ Wout, const float* __restrict__ Wvi,
                       const float* __restrict__ bvi, const float* __restrict__ bout) {
    int o = blockIdx.x, i = threadIdx.x;
    float acc = 0.f;
    for (int m = 0; m < CC; m++) acc += Wout[o*CC + m] * Wvi[m*CC + i];
    g_Wc[o*CC + i] = acc;
    if (i == 0) {
        float b = bout[o];
        for (int m = 0; m < CC; m++) b += Wout[o*CC + m] * bvi[m];
        g_beff[o] = b;
    }
}

// split-bf16 GEMM mainloop: per-warp MFx NF fragment tile
template<int MF, int NF, int KT, int XP, int KPW>
__device__ __forceinline__ void gemm_ms(const __nv_bfloat16* __restrict__ Wh,
                                        const __nv_bfloat16* __restrict__ Wl,
                                        const float* __restrict__ Xs,
                                        float C[MF][NF][4], int m0, int n0, int lane) {
    const int lrow = (lane & 7) + ((lane >> 3) & 1) * 8;
    const int lk8  = ((lane >> 4) & 1) * 8;
    const int bn   = n0 + (lane >> 2);
    const int bk   = 2 * (lane & 3);
    for (int ks = 0; ks < KT/16; ks++) {
        u32 ah[MF][4], al[MF][4];
        #pragma unroll
        for (int i = 0; i < MF; i++) {
            int off = (m0 + i*16 + lrow)*KPW + ks*16 + lk8;
            ldsm4(ah[i], Wh + off);
            ldsm4(al[i], Wl + off);
        }
        u32 bh[NF][2], bl[NF][2];
        #pragma unroll
        for (int j = 0; j < NF; j++) {
            const float* xp = Xs + (ks*16 + bk)*XP + bn + j*8;
            float x0 = xp[0], x1 = xp[XP], x2 = xp[8*XP], x3 = xp[9*XP];
            u32 h0 = cvt2(x1, x0), h1 = cvt2(x3, x2);
            float hl0 = __uint_as_float(h0 << 16), hh0 = __uint_as_float(h0 & 0xFFFF0000u);
            float hl1 = __uint_as_float(h1 << 16), hh1 = __uint_as_float(h1 & 0xFFFF0000u);
            bh[j][0] = h0; bh[j][1] = h1;
            bl[j][0] = cvt2(x1 - hh0, x0 - hl0);
            bl[j][1] = cvt2(x3 - hh1, x2 - hl1);
        }
        #pragma unroll
        for (int i = 0; i < MF; i++)
            #pragma unroll
            for (int j = 0; j < NF; j++) mma16816(C[i][j], ah[i], bh[j][0], bh[j][1]);
        #pragma unroll
        for (int i = 0; i < MF; i++)
            #pragma unroll
            for (int j = 0; j < NF; j++) mma16816(C[i][j], ah[i], bl[j][0], bl[j][1]);
        #pragma unroll
        for (int i = 0; i < MF; i++)
            #pragma unroll
            for (int j = 0; j < NF; j++) mma16816(C[i][j], al[i], bh[j][0], bh[j][1]);
    }
}

__device__ __forceinline__ void w_split(float w, __nv_bfloat16* Wh, __nv_bfloat16* Wl, int off) {
    __nv_bfloat16 h = __float2bfloat16(w);
    Wh[off] = h;
    Wl[off] = __float2bfloat16(w - __bfloat162float(h));
}

// K1: coarse k,v. M=192, K=128, BN=32 px/tile. Persistent.
#define KV_SMEM (192*136*2*2 + 2*128*36*4 + 32*196*4)
__global__ void __launch_bounds__(256) k_kv(const float* __restrict__ hp,
        const float* __restrict__ Wk, const float* __restrict__ bk,
        const float* __restrict__ Wvp, const float* __restrict__ bvp) {
    extern __shared__ char smraw[];
    __nv_bfloat16* Wh = (__nv_bfloat16*)smraw;
    __nv_bfloat16* Wl = Wh + 192*136;
    float* Xs = (float*)(smraw + 192*136*2*2);
    float* Ss = Xs + 2*128*36;
    int t = threadIdx.x;

    for (int idx = t; idx < 192*128; idx += 256) {
        int m = idx >> 7, k = idx & 127;
        float w = (m < 64) ? Wk[m*128 + k] : Wvp[(m - 64)*128 + k];
        w_split(w, Wh, Wl, m*136 + k);
    }
    const int NT = NPIX2/32;
    auto load_tile = [&](int buf, int tile) {
        float* X = Xs + buf*128*36;
        int p0 = tile*32, bb = p0 >> 15, s0 = p0 & (HW2 - 1);
        const float* hb = hp + (size_t)bb*128*HW2 + s0;
        #pragma unroll
        for (int c8 = 0; c8 < 4; c8++) {
            int chunk = t + 256*c8;
            int r = chunk >> 3, q = chunk & 7;
            cpa16(X + r*36 + q*4, hb + (size_t)r*HW2 + q*4);
        }
    };
    int lane = t & 31, warp = t >> 5;
    int wm = warp >> 1, wn = warp & 1;
    int m0 = wm*48, n0 = wn*16;
    int r0 = m0 + (lane >> 2);

    int tile = blockIdx.x, par = 0;
    if (tile < NT) load_tile(0, tile);
    CPA_COMMIT();
    __syncthreads();
    for (; tile < NT; tile += GRD) {
        int nxt = tile + GRD;
        if (nxt < NT) load_tile(par ^ 1, nxt);
        CPA_COMMIT();
        CPA_WAIT1();
        __syncthreads();

        float C[3][2][4];
        #pragma unroll
        for (int i = 0; i < 3; i++) {
            int ra = r0 + i*16, rb = ra + 8;
            float b0 = (ra < 64) ? bk[ra] : bvp[ra - 64];
            float b1 = (rb < 64) ? bk[rb] : bvp[rb - 64];
            #pragma unroll
            for (int j = 0; j < 2; j++) {
                C[i][j][0] = C[i][j][1] = b0;
                C[i][j][2] = C[i][j][3] = b1;
            }
        }
        gemm_ms<3,2,128,36,136>(Wh, Wl, Xs + par*128*36, C, m0, n0, lane);
        __syncthreads();
        #pragma unroll
        for (int i = 0; i < 3; i++)
            #pragma unroll
            for (int j = 0; j < 2; j++) {
                int pc = n0 + j*8 + 2*(lane & 3);
                int rr = m0 + i*16 + (lane >> 2);
                Ss[pc*196 + rr]           = C[i][j][0];
                Ss[(pc + 1)*196 + rr]     = C[i][j][1];
                Ss[pc*196 + rr + 8]       = C[i][j][2];
                Ss[(pc + 1)*196 + rr + 8] = C[i][j][3];
            }
        __syncthreads();
        int p0 = tile*32;
        #pragma unroll
        for (int c = 0; c < 2; c++) {
            int idx = t + 256*c;
            int p = idx >> 4, f4 = idx & 15;
            float4 v = *(const float4*)(Ss + p*196 + f4*4);
            *(float4*)(g_k + (size_t)(p0 + p)*64 + f4*4) = v;
        }
        #pragma unroll
        for (int c = 0; c < 4; c++) {
            int idx = t + 256*c;
            int p = idx >> 5, f5 = idx & 31;
            float4 v = *(const float4*)(Ss + p*196 + 64 + f5*4);
            *(float4*)(g_v + (size_t)(p0 + p)*128 + f5*4) = v;
        }
        __syncthreads();
        par ^= 1;
    }
}

// K2: q. M=64, K=128, BN=128 px/tile. Persistent.
#define Q_SMEM (64*136*2*2 + 2*128*132*4 + 128*68*4)
__global__ void __launch_bounds__(256) k_q(const float* __restrict__ hi,
        const float* __restrict__ Wq, const float* __restrict__ bq) {
    extern __shared__ char smraw[];
    __nv_bfloat16* Wh = (__nv_bfloat16*)smraw;
    __nv_bfloat16* Wl = Wh + 64*136;
    float* Xs = (float*)(smraw + 64*136*2*2);
    float* Ss = Xs + 2*128*132;
    int t = threadIdx.x;

    for (int idx = t; idx < 64*128; idx += 256) {
        int m = idx >> 7, k = idx & 127;
        w_split(Wq[idx], Wh, Wl, m*136 + k);
    }
    const int NT = NPIXF/128;
    auto load_tile = [&](int buf, int tile) {
        float* X = Xs + buf*128*132;
        int p0 = tile*128, bb = p0 >> 17, s0 = p0 & (HWF - 1);
        const float* hb = hi + (size_t)bb*128*HWF + s0;
        #pragma unroll
        for (int c8 = 0; c8 < 16; c8++) {
            int chunk = t + 256*c8;
            int r = chunk >> 5, q = chunk & 31;
            cpa16(X + r*132 + q*4, hb + (size_t)r*HWF + q*4);
        }
    };
    int lane = t & 31, warp = t >> 5;
    int wm = warp >> 2, wn = warp & 3;
    int m0 = wm*32, n0 = wn*32;
    int r0 = m0 + (lane >> 2);

    int tile = blockIdx.x, par = 0;
    if (tile < NT) load_tile(0, tile);
    CPA_COMMIT();
    __syncthreads();
    for (; tile < NT; tile += GRD) {
        int nxt = tile + GRD;
        if (nxt < NT) load_tile(par ^ 1, nxt);
        CPA_COMMIT();
        CPA_WAIT1();
        __syncthreads();

        float C[2][4][4];
        #pragma unroll
        for (int i = 0; i < 2; i++) {
            float b0 = bq[r0 + i*16], b1 = bq[r0 + i*16 + 8];
            #pragma unroll
            for (int j = 0; j < 4; j++) {
                C[i][j][0] = C[i][j][1] = b0;
                C[i][j][2] = C[i][j][3] = b1;
            }
        }
        gemm_ms<2,4,128,132,136>(Wh, Wl, Xs + par*128*132, C, m0, n0, lane);
        __syncthreads();
        #pragma unroll
        for (int i = 0; i < 2; i++)
            #pragma unroll
            for (int j = 0; j < 4; j++) {
                int pc = n0 + j*8 + 2*(lane & 3);
                int rr = m0 + i*16 + (lane >> 2);
                Ss[pc*68 + rr]           = C[i][j][0];
                Ss[(pc + 1)*68 + rr]     = C[i][j][1];
                Ss[pc*68 + rr + 8]       = C[i][j][2];
                Ss[(pc + 1)*68 + rr + 8] = C[i][j][3];
            }
        __syncthreads();
        int p0 = tile*128;
        #pragma unroll
        for (int c = 0; c < 8; c++) {
            int idx = t + 256*c;
            int p = idx >> 4, f4 = idx & 15;
            float4 v = *(const float4*)(Ss + p*68 + f4*4);
            *(float4*)(g_q + (size_t)(p0 + p)*64 + f4*4) = v;
        }
        __syncthreads();
        par ^= 1;
    }
}

// K3: attention, writes g_x NCHW
#define ATTN_SMEM ((NH*KP + NH*VP + 256*AP)*4)
__global__ void __launch_bounds__(256) k_attn() {
    extern __shared__ float sm[];
    float* ks = sm;
    float* vs = ks + NH*KP;
    float* as = vs + NH*VP;
    int t = threadIdx.x;
    int b = blockIdx.z;
    int cy0 = blockIdx.y * CTY, cx0 = blockIdx.x * CTX;
    int fy0 = cy0*2, fx0 = cx0*2;

    for (int idx = t; idx < NH*CCK; idx += 256) {
        int pix = idx >> 6, c = idx & 63;
        int hy = pix / HX, hx = pix % HX;
        int gy = cy0 + hy - 1, gx = cx0 + hx - 1;
        float v = 0.f;
        if ((unsigned)gy < CH2 && (unsigned)gx < CW2)
            v = g_k[((size_t)(b*HW2 + gy*CW2 + gx))*CCK + c];
        ks[pix*KP + c] = v;
    }
    for (int idx = t; idx < NH*CC; idx += 256) {
        int pix = idx >> 7, c = idx & 127;
        int hy = pix / HX, hx = pix % HX;
        int gy = cy0 + hy - 1, gx = cx0 + hx - 1;
        float v = 0.f;
        if ((unsigned)gy < CH2 && (unsigned)gx < CW2)
            v = g_v[((size_t)(b*HW2 + gy*CW2 + gx))*CC + c];
        vs[pix*VP + c] = v;
    }
    __syncthreads();

    {   // Phase A
        int p = t;
        int fy = p >> 5, fx = p & 31;
        int cy = fy >> 1, cx = fx >> 1;
        const float4* gq = reinterpret_cast<const float4*>(
            g_q + ((size_t)((b*CH + fy0 + fy)*CW + fx0 + fx))*CCK);
        const float* kb = ks + (cy*HX + cx)*KP;
        ull sc2[9];
        #pragma unroll
        for (int j = 0; j < 9; j++) sc2[j] = 0ull;
        #pragma unroll 4
        for (int cc = 0; cc < 16; cc++) {
            float4 q4 = gq[cc];
            ull qa = pk2p(q4.x, q4.y);
            ull qb = pk2p(q4.z, q4.w);
            int c = cc*4;
            #pragma unroll
            for (int dy = 0; dy < 3; dy++)
                #pragma unroll
                for (int dx = 0; dx < 3; dx++) {
                    int j = dy*3 + dx;
                    const float* kp = kb + (dy*HX + dx)*KP + c;
                    sc2[j] = fma2(qa, ld2(kp), sc2[j]);
                    sc2[j] = fma2(qb, ld2(kp + 2), sc2[j]);
                }
        }
        float sc[9];
        #pragma unroll
        for (int j = 0; j < 9; j++) { float2 v = upk(sc2[j]); sc[j] = v.x + v.y; }
        float m = sc[0];
        #pragma unroll
        for (int j = 1; j < 9; j++) m = fmaxf(m, sc[j]);
        float s = 0.f;
        #pragma unroll
        for (int j = 0; j < 9; j++) { sc[j] = __expf(sc[j] - m); s += sc[j]; }
        float inv = 1.f / s;
        #pragma unroll
        for (int j = 0; j < 9; j++) as[p*AP + j] = sc[j]*inv;
    }
    __syncthreads();

    {   // Phase B: thread = coarse cell (4 px) x 32 channels
        int cell = t & 63, cg = t >> 6;
        int cyl = cell >> 4, cxl = cell & 15;
        ull a01[9], a23[9];
        int p00 = (2*cyl)*32 + 2*cxl;
        int p10 = p00 + 32;
        #pragma unroll
        for (int j = 0; j < 9; j++) {
            a01[j] = pk2p(as[p00*AP + j], as[(p00 + 1)*AP + j]);
            a23[j] = pk2p(as[p10*AP + j], as[(p10 + 1)*AP + j]);
        }
        const float* vb = vs + (cyl*HX + cxl)*VP + cg*32;
        size_t obase = ((size_t)(b*CC + cg*32))*HWF
                     + (size_t)(fy0 + 2*cyl)*CW + fx0 + 2*cxl;
        for (int cc = 0; cc < 32; cc++) {
            ull o01 = 0ull, o23 = 0ull;
            #pragma unroll
            for (int dy = 0; dy < 3; dy++)
                #pragma unroll
                for (int dx = 0; dx < 3; dx++) {
                    int j = dy*3 + dx;
                    ull vv = pk2(vb[(dy*HX + dx)*VP + cc]);
                    o01 = fma2(a01[j], vv, o01);
                    o23 = fma2(a23[j], vv, o23);
                }
            size_t oa = obase + (size_t)cc*HWF;
            *reinterpret_cast<float2*>(g_x + oa)      = upk(o01);
            *reinterpret_cast<float2*>(g_x + oa + CW) = upk(o23);
        }
    }
}

// K4: out. M=128, K=256, BN=32 px/tile. Persistent, NCHW direct store.
#define O_SMEM (128*264*2*2 + 2*256*36*4)
__global__ void __launch_bounds__(256) k_out(const float* __restrict__ hi,
        const float* __restrict__ Wout, float* __restrict__ out) {
    extern __shared__ char smraw[];
    __nv_bfloat16* Wh = (__nv_bfloat16*)smraw;
    __nv_bfloat16* Wl = Wh + 128*264;
    float* Xs = (float*)(smraw + 128*264*2*2);
    int t = threadIdx.x;

    for (int idx = t; idx < 128*256; idx += 256) {
        int m = idx >> 8, k = idx & 255;
        float w = (k < 128) ? g_Wc[m*128 + k] : Wout[m*128 + (k - 128)];
        w_split(w, Wh, Wl, m*264 + k);
    }
    const int NT = NPIXF/32;
    auto load_tile = [&](int buf, int tile) {
        float* X = Xs + buf*256*36;
        int p0 = tile*32, bb = p0 >> 17, s0 = p0 & (HWF - 1);
        const float* hb = hi + (size_t)bb*128*HWF + s0;
        const float* xb = g_x + (size_t)bb*128*HWF + s0;
        #pragma unroll
        for (int c8 = 0; c8 < 8; c8++) {
            int chunk = t + 256*c8;
            int r = chunk >> 3, q = chunk & 7;
            const float* src = (r < 128) ? hb + (size_t)r*HWF + q*4
                                         : xb + (size_t)(r - 128)*HWF + q*4;
            cpa16(X + r*36 + q*4, src);
        }
    };
    int lane = t & 31, warp = t >> 5;
    int wm = warp >> 1, wn = warp & 1;
    int m0 = wm*32, n0 = wn*16;
    int r0 = m0 + (lane >> 2);

    int tile = blockIdx.x, par = 0;
    if (tile < NT) load_tile(0, tile);
    CPA_COMMIT();
    __syncthreads();
    for (; tile < NT; tile += GRD) {
        int nxt = tile + GRD;
        if (nxt < NT) load_tile(par ^ 1, nxt);
        CPA_COMMIT();
        CPA_WAIT1();
        __syncthreads();

        float C[2][2][4];
        #pragma unroll
        for (int i = 0; i < 2; i++) {
            float b0 = g_beff[r0 + i*16], b1 = g_beff[r0 + i*16 + 8];
            #pragma unroll
            for (int j = 0; j < 2; j++) {
                C[i][j][0] = C[i][j][1] = b0;
                C[i][j][2] = C[i][j][3] = b1;
            }
        }
        gemm_ms<2,2,256,36,264>(Wh, Wl, Xs + par*256*36, C, m0, n0, lane);

        int p0 = tile*32, bb = p0 >> 17, s0 = p0 & (HWF - 1);
        float* ob = out + (size_t)bb*128*HWF + s0;
        int cb = n0 + 2*(lane & 3);
        #pragma unroll
        for (int i = 0; i < 2; i++) {
            int r = r0 + i*16;
            #pragma unroll
            for (int j = 0; j < 2; j++) {
                int ccol = cb + j*8;
                *(float2*)(ob + (size_t)r*HWF + ccol)       = make_float2(C[i][j][0], C[i][j][1]);
                *(float2*)(ob + (size_t)(r + 8)*HWF + ccol) = make_float2(C[i][j][2], C[i][j][3]);
            }
        }
        __syncthreads();
        par ^= 1;
    }
}

extern "C" void kernel_launch(void* const* d_in, const int* in_sizes, int n_in,
                              void* d_out, int out_size) {
    const float* h_prev = (const float*)d_in[0];
    const float* h_init = (const float*)d_in[1];
    const float* Wq   = (const float*)d_in[2];
    const float* bq   = (const float*)d_in[3];
    const float* Wk   = (const float*)d_in[4];
    const float* bk   = (const float*)d_in[5];
    const float* Wvp  = (const float*)d_in[6];
    const float* bvp  = (const float*)d_in[7];
    const float* Wvi  = (const float*)d_in[8];
    const float* bvi  = (const float*)d_in[9];
    const float* Wout = (const float*)d_in[10];
    const float* bout = (const float*)d_in[11];
    float* out = (float*)d_out;

    cudaFuncSetAttribute(k_kv,   cudaFuncAttributeMaxDynamicSharedMemorySize, KV_SMEM);
    cudaFuncSetAttribute(k_q,    cudaFuncAttributeMaxDynamicSharedMemorySize, Q_SMEM);
    cudaFuncSetAttribute(k_attn, cudaFuncAttributeMaxDynamicSharedMemorySize, ATTN_SMEM);
    cudaFuncSetAttribute(k_out,  cudaFuncAttributeMaxDynamicSharedMemorySize, O_SMEM);

    k_fuse<<<CC, CC>>>(Wout, Wvi, bvi, bout);
    k_kv<<<GRD, 256, KV_SMEM>>>(h_prev, Wk, bk, Wvp, bvp);
    k_q<<<GRD, 256, Q_SMEM>>>(h_init, Wq, bq);
    dim3 ag(CW2/CTX, CH2/CTY, CB);
    k_attn<<<ag, 256, ATTN_SMEM>>>();
    k_out<<<GRD, 256, O_SMEM>>>(h_init, Wout, out);
}